// round 16
// baseline (speedup 1.0000x reference)
#include <cuda_runtime.h>
#include <cuda_bf16.h>
#include <cuda_fp8.h>
#include <math.h>
#include <cstdint>

#define B_ 2
#define L_ 256
#define H_ 256
#define C_ 5
#define VOCAB 255

#define BSCALE 256.0f
#define BINV   (1.0f / 256.0f)

// ---- scratch (no cudaMalloc allowed) ----
__device__ __align__(16) float g_Rt[VOCAB * H_];             // bias-init + split-K accum
__device__ __align__(16) __nv_bfloat16 g_Rth[VOCAB * H_];    // bf16 rel term
__device__ __align__(16) float g_A [B_ * L_ * H_];           // hs @ (We + Wd)
__device__ __align__(16) __nv_bfloat16 g_Bvh[B_ * L_ * H_];  // bf16 hs @ (Ws - Wd)
__device__ __align__(16) __nv_bfloat16 g_hsb[B_ * L_ * H_];  // bf16 hidden_state
__device__ __align__(16) uint16_t g_Wm8i[(H_ / 2) * H_];     // fp8 Wm*256, k-pair interleaved: [k2][h]

// cvt: byte1 = a (odd k), byte0 = b (even k)
__device__ __forceinline__ uint16_t cvt_e4m3x2(float a_hi, float b_lo) {
    uint16_t r;
    asm("cvt.rn.satfinite.e4m3x2.f32 %0, %1, %2;" : "=h"(r) : "f"(a_hi), "f"(b_lo));
    return r;
}

// ---------------------------------------------------------------------------
// prep: hsb bf16, Wm fp8 (scaled, k-pair interleaved), g_Rt := bias
// ---------------------------------------------------------------------------
__global__ void prep_kernel(const float* __restrict__ hs,
                            const float* __restrict__ Wh_w,
                            const float* __restrict__ Wh_b) {
    int idx = blockIdx.x * 256 + threadIdx.x;
    if (idx < B_ * L_ * H_) {
        g_hsb[idx] = __float2bfloat16(hs[idx]);
        return;
    }
    int r = idx - B_ * L_ * H_;
    if (r < (H_ / 2) * H_) {          // r = k2*256 + h
        int k2 = r >> 8, h = r & 255;
        const float* Wm = Wh_w + 3 * H_ * H_;
        float we = Wm[(2 * k2) * H_ + h] * BSCALE;
        float wo = Wm[(2 * k2 + 1) * H_ + h] * BSCALE;
        g_Wm8i[r] = cvt_e4m3x2(wo, we);
        return;
    }
    int r2 = r - (H_ / 2) * H_;
    if (r2 < VOCAB * H_)
        g_Rt[r2] = Wh_b[r2 & 255];
}

// ---------------------------------------------------------------------------
// relterm split-K: grid (51, 4); atomicAdd into bias-initialized g_Rt.
// ---------------------------------------------------------------------------
__global__ void relterm_kernel(const float* __restrict__ Wh_w) {
    __shared__ float tbl[5][H_];
    const int d0 = blockIdx.x * 5;
    const int kq = blockIdx.y;
    const int h  = threadIdx.x;
    const float cst = -logf(10000.0f) / (float)(4 * H_);
    {
        int kg = kq * 256 + h;
        int kk = kg & ~1;
        float w = expf(cst * (float)kk);
        #pragma unroll
        for (int r = 0; r < 5; r++) {
            float ang = (float)(d0 + r) * w;
            tbl[r][h] = (kg & 1) ? cosf(ang) : sinf(ang);
        }
    }
    __syncthreads();
    float a[5] = {0.f, 0.f, 0.f, 0.f, 0.f};
    #pragma unroll 4
    for (int k = 0; k < 256; k++) {
        float wv = Wh_w[(kq * 256 + k) * H_ + h];
        #pragma unroll
        for (int r = 0; r < 5; r++)
            a[r] = fmaf(tbl[r][k], wv, a[r]);
    }
    #pragma unroll
    for (int r = 0; r < 5; r++)
        atomicAdd(&g_Rt[(d0 + r) * H_ + h], a[r]);
}

__global__ void rtcvt_kernel() {
    int idx = blockIdx.x * 256 + threadIdx.x;
    if (idx < VOCAB * H_)
        g_Rth[idx] = __float2bfloat16(g_Rt[idx]);
}

// ---------------------------------------------------------------------------
// A[r,h] = hs@(We+Wd) fp32 ;  Bv[r,h] = hs@(Ws-Wd) bf16. 8 rows/block.
// ---------------------------------------------------------------------------
__global__ void abv_kernel(const float* __restrict__ hs,
                           const float* __restrict__ Wh_w) {
    __shared__ float rows[8][H_];
    int rb = blockIdx.x * 8;
    int h  = threadIdx.x;
    #pragma unroll
    for (int r = 0; r < 8; r++)
        rows[r][h] = hs[(rb + r) * H_ + h];
    __syncthreads();
    float accA[8], accB[8];
    #pragma unroll
    for (int r = 0; r < 8; r++) { accA[r] = 0.f; accB[r] = 0.f; }
    #pragma unroll 2
    for (int k = 0; k < H_; k++) {
        float we = Wh_w[(0 * H_ + k) * H_ + h];
        float ws = Wh_w[(1 * H_ + k) * H_ + h];
        float wd = Wh_w[(2 * H_ + k) * H_ + h];
        float wa = we + wd, wb = ws - wd;
        #pragma unroll
        for (int r = 0; r < 8; r++) {
            float v = rows[r][k];
            accA[r] = fmaf(v, wa, accA[r]);
            accB[r] = fmaf(v, wb, accB[r]);
        }
    }
    #pragma unroll
    for (int r = 0; r < 8; r++) {
        g_A  [(rb + r) * H_ + h] = accA[r];
        g_Bvh[(rb + r) * H_ + h] = __float2bfloat16(accB[r]);
    }
}

// ---------------------------------------------------------------------------
// out init: Wo_b - 1e12*tril - inf*mask. Mains atomicAdd pure partials.
// ---------------------------------------------------------------------------
__global__ void outinit_kernel(const int* __restrict__ mask,
                               const float* __restrict__ Wo_b,
                               float* __restrict__ out) {
    int idx = blockIdx.x * 256 + threadIdx.x;
    if (idx >= B_ * C_ * L_ * L_) return;
    int j = idx & 255;
    int i = (idx >> 8) & 255;
    int c = (idx >> 16) % C_;
    int b = idx / (C_ * L_ * L_);
    float v = Wo_b[c];
    if (i > j) v -= 1e12f;
    if (!mask[b * L_ + i] || !mask[b * L_ + j]) v = -INFINITY;
    out[idx] = v;
}

// ---------------------------------------------------------------------------
// main: fp8 e4m3 mma.sync m16n8k32. Block = (jt*2+ht, ich, b), NI=4 i's.
//   B = Wm (i-invariant, staged ONCE); A'[j,k] = hs_j*hs_i restaged per i.
//   pre = acc/256 + A_i[h] + Bv[j,h] + Rt[d,h] -> tanh -> @Wo (C=5)
//   85.5KB smem + 64 regs -> 2 blocks/SM co-residency.
// ---------------------------------------------------------------------------
#define NT  512
#define NI  4
#define SSB 136   // b16-unit stride (272B rows): row starts 4 banks apart

// dynamic smem (bytes)
#define OFF_BS   0                    // 128*136*2 = 34816
#define OFF_AS   34816                // 34816
#define OFF_WO   69632                // 4096
#define OFF_AI   73728                // 512
#define OFF_HI   74240                // 1024 (hi as f32)
#define OFF_RED  75264                // 4*128*5*4 = 10240
#define SMEM_TOTAL 85504

__device__ __forceinline__ float tanha(float x) {
    float r; asm("tanh.approx.f32 %0, %1;" : "=f"(r) : "f"(x)); return r;
}
__device__ __forceinline__ void ldsm4(unsigned r[4], uint32_t a) {
    asm volatile("ldmatrix.sync.aligned.m8n8.x4.shared.b16 {%0,%1,%2,%3}, [%4];"
                 : "=r"(r[0]), "=r"(r[1]), "=r"(r[2]), "=r"(r[3]) : "r"(a));
}
__device__ __forceinline__ void ldsm4t(unsigned r[4], uint32_t a) {
    asm volatile("ldmatrix.sync.aligned.m8n8.x4.trans.shared.b16 {%0,%1,%2,%3}, [%4];"
                 : "=r"(r[0]), "=r"(r[1]), "=r"(r[2]), "=r"(r[3]) : "r"(a));
}
__device__ __forceinline__ void mma_fp8(float d[4], const unsigned a[4], const unsigned b[2]) {
    asm volatile("mma.sync.aligned.m16n8k32.row.col.f32.e4m3.e4m3.f32 "
                 "{%0,%1,%2,%3}, {%4,%5,%6,%7}, {%8,%9}, {%0,%1,%2,%3};"
                 : "+f"(d[0]), "+f"(d[1]), "+f"(d[2]), "+f"(d[3])
                 : "r"(a[0]), "r"(a[1]), "r"(a[2]), "r"(a[3]), "r"(b[0]), "r"(b[1]));
}

__global__ __launch_bounds__(NT, 2)
void main_kernel(const float* __restrict__ Wo_w,
                 float* __restrict__ out) {
    extern __shared__ __align__(16) char dynS[];
    uint16_t* Bs  = (uint16_t*)(dynS + OFF_BS);   // [k2=128][h=128] b16 (fp8 pairs)
    uint16_t* As  = (uint16_t*)(dynS + OFF_AS);   // [j=128][k2=128] b16 (fp8 pairs)
    float*    woS = (float*)   (dynS + OFF_WO);
    float*    aiS = (float*)   (dynS + OFF_AI);
    float*    hiS = (float*)   (dynS + OFF_HI);
    float*    red = (float*)   (dynS + OFF_RED);

    const int jh = blockIdx.x;
    const int jt = jh >> 1, ht = jh & 1;
    const int ich = blockIdx.y, b = blockIdx.z;
    const int jbase = jt * 128, hbase = ht * 128;
    const int tid  = threadIdx.x;
    const int lane = tid & 31, warp = tid >> 5;
    const int wm = warp >> 2, wn = warp & 3;

    // ---- stage B = Wm8i h-half (pure copy, once) + Wo half ----
    #pragma unroll
    for (int p = 0; p < 4; p++) {
        int task = tid + p * NT;              // 2048 uint4 tasks
        int k2 = task >> 4, seg = task & 15;  // 16 segs x 8 b16 = 128 h
        *(uint4*)&Bs[k2 * SSB + seg * 8] =
            *(const uint4*)&g_Wm8i[k2 * H_ + hbase + seg * 8];
    }
    for (int t = tid; t < 128 * C_; t += NT)
        woS[(t / C_) * 8 + (t % C_)] = Wo_w[(hbase + t / C_) * C_ + (t % C_)];

    const uint32_t AsA = (uint32_t)__cvta_generic_to_shared(As);
    const uint32_t BsA = (uint32_t)__cvta_generic_to_shared(Bs);
    const int g  = lane >> 3, r8 = lane & 7;
    const int arow  = ((g & 1) << 3) + r8;
    const int acolg = (g >> 1) << 3;
    const int browg = ((g & 1) << 3) + r8;
    const int bcol  = (g >> 1) << 3;

    // A' staging map: 4 threads per j-row (coalesced LDG)
    const int sj = tid >> 2;
    const int kb = (tid & 3) * 64;            // fp8 k base (64 fp8 = 32 b16)
    const __nv_bfloat162* hsrow =
        (const __nv_bfloat162*)&g_hsb[(b * L_ + jbase + sj) * H_ + kb];

    for (int it = 0; it < NI; it++) {
        const int i = ich * NI + it;

        // ---- per-i small stages ----
        if (tid < 256) hiS[tid] = __bfloat162float(g_hsb[(b * L_ + i) * H_ + tid]);
        if (tid < 128) aiS[tid] = g_A[(b * L_ + i) * H_ + hbase + tid];
        __syncthreads();   // hiS ready (also isolates As rewrite from prior i readers)

        // ---- stage A'[j][k] = e4m3(hs_j[k] * hi[k]), k-pair packed b16 ----
        {
            const float2* hi2 = (const float2*)&hiS[kb];
            #pragma unroll
            for (int q = 0; q < 4; q++) {       // 4 x uint4 = 32 b16 = 64 fp8
                uint16_t o[8];
                #pragma unroll
                for (int e = 0; e < 8; e++) {
                    float2 hf = __bfloat1622float2(hsrow[q * 8 + e]);
                    float2 gi = hi2[q * 8 + e];
                    o[e] = cvt_e4m3x2(hf.y * gi.y, hf.x * gi.x);
                }
                *(uint4*)&As[sj * SSB + (kb >> 1) + q * 8] = *(uint4*)o;
            }
        }
        __syncthreads();

        // ---- MMA loop: K=256 fp8 = 128 b16 cols, 8 iterations of k32 ----
        float acc[2][4][4];
        #pragma unroll
        for (int mt = 0; mt < 2; mt++)
            #pragma unroll
            for (int nt = 0; nt < 4; nt++)
                #pragma unroll
                for (int q = 0; q < 4; q++) acc[mt][nt][q] = 0.f;

        #pragma unroll
        for (int ks2 = 0; ks2 < 128; ks2 += 16) {
            unsigned af[2][4], bfr[4][2];
            #pragma unroll
            for (int mt = 0; mt < 2; mt++)
                ldsm4(af[mt], AsA + (((wm * 32 + mt * 16 + arow) * SSB + ks2 + acolg) << 1));
            #pragma unroll
            for (int p = 0; p < 2; p++) {
                unsigned q[4];
                ldsm4t(q, BsA + (((ks2 + browg) * SSB + wn * 32 + p * 16 + bcol) << 1));
                bfr[2 * p][0] = q[0]; bfr[2 * p][1] = q[1];
                bfr[2 * p + 1][0] = q[2]; bfr[2 * p + 1][1] = q[3];
            }
            #pragma unroll
            for (int mt = 0; mt < 2; mt++)
                #pragma unroll
                for (int nt = 0; nt < 4; nt++)
                    mma_fp8(acc[mt][nt], af[mt], bfr[nt]);
        }

        // ---- fused epilogue ----
        float ps[4][C_];
        #pragma unroll
        for (int ri = 0; ri < 4; ri++)
            #pragma unroll
            for (int cc = 0; cc < C_; cc++) ps[ri][cc] = 0.f;

        const int rb = lane >> 2, qc = (lane & 3) * 2;
        #pragma unroll
        for (int nt = 0; nt < 4; nt++) {
            int c = wn * 32 + nt * 8 + qc;
            float ai0 = aiS[c], ai1 = aiS[c + 1];
            float4 wv0 = *(const float4*)&woS[c * 8];
            float  w04 = woS[c * 8 + 4];
            float4 wv1 = *(const float4*)&woS[(c + 1) * 8];
            float  w14 = woS[(c + 1) * 8 + 4];
            float w0[5] = {wv0.x, wv0.y, wv0.z, wv0.w, w04};
            float w1[5] = {wv1.x, wv1.y, wv1.z, wv1.w, w14};
            #pragma unroll
            for (int mt = 0; mt < 2; mt++) {
                int r0 = wm * 32 + mt * 16 + rb;
                int r1 = r0 + 8;
                int j0 = jbase + r0, j1 = jbase + r1;
                int d0 = min(max(j0 - i, -127), 127) + 127;
                int d1 = min(max(j1 - i, -127), 127) + 127;
                float2 R0 = __bfloat1622float2(
                    *(const __nv_bfloat162*)&g_Rth[d0 * H_ + hbase + c]);
                float2 R1 = __bfloat1622float2(
                    *(const __nv_bfloat162*)&g_Rth[d1 * H_ + hbase + c]);
                float2 V0 = __bfloat1622float2(
                    *(const __nv_bfloat162*)&g_Bvh[(b * L_ + j0) * H_ + hbase + c]);
                float2 V1 = __bfloat1622float2(
                    *(const __nv_bfloat162*)&g_Bvh[(b * L_ + j1) * H_ + hbase + c]);
                const float* a4 = acc[mt][nt];
                float t00 = tanha(fmaf(a4[0], BINV, ai0 + V0.x + R0.x));
                float t01 = tanha(fmaf(a4[1], BINV, ai1 + V0.y + R0.y));
                float t10 = tanha(fmaf(a4[2], BINV, ai0 + V1.x + R1.x));
                float t11 = tanha(fmaf(a4[3], BINV, ai1 + V1.y + R1.y));
                #pragma unroll
                for (int cc = 0; cc < C_; cc++) {
                    ps[2 * mt][cc]     = fmaf(t00, w0[cc], fmaf(t01, w1[cc], ps[2 * mt][cc]));
                    ps[2 * mt + 1][cc] = fmaf(t10, w0[cc], fmaf(t11, w1[cc], ps[2 * mt + 1][cc]));
                }
            }
        }

        // quad-reduce, per-wn disjoint red slices
        #pragma unroll
        for (int ri = 0; ri < 4; ri++) {
            int row = wm * 32 + (ri >> 1) * 16 + (ri & 1) * 8 + rb;
            #pragma unroll
            for (int cc = 0; cc < C_; cc++) {
                float v = ps[ri][cc];
                v += __shfl_xor_sync(0xffffffffu, v, 1);
                v += __shfl_xor_sync(0xffffffffu, v, 2);
                if ((lane & 3) == 0) red[(wn * 128 + row) * C_ + cc] = v;
            }
        }
        __syncthreads();

        // final 4-slice sum + global atomic into pre-initialized out
        if (tid < 128) {
            const int j = jbase + tid;
            float* op = &out[((b * C_ + 0) * L_ + i) * L_ + j];
            #pragma unroll
            for (int cc = 0; cc < C_; cc++) {
                float v = red[tid * C_ + cc] + red[(128 + tid) * C_ + cc]
                        + red[(256 + tid) * C_ + cc] + red[(384 + tid) * C_ + cc];
                atomicAdd(op + cc * L_ * L_, v);
            }
        }
    }
}

// ---------------------------------------------------------------------------
extern "C" void kernel_launch(void* const* d_in, const int* in_sizes, int n_in,
                              void* d_out, int out_size) {
    const float* hs   = (const float*)d_in[0];
    const int*   mask = (const int*)  d_in[1];
    const float* Wh_w = (const float*)d_in[2];
    const float* Wh_b = (const float*)d_in[3];
    const float* Wo_w = (const float*)d_in[4];
    const float* Wo_b = (const float*)d_in[5];
    float* out = (float*)d_out;

    cudaFuncSetAttribute(main_kernel,
                         cudaFuncAttributeMaxDynamicSharedMemorySize, SMEM_TOTAL);

    int prep_elems = B_ * L_ * H_ + (H_ / 2) * H_ + VOCAB * H_;
    prep_kernel<<<(prep_elems + 255) / 256, 256>>>(hs, Wh_w, Wh_b);
    dim3 rg(51, 4);
    relterm_kernel<<<rg, H_>>>(Wh_w);
    rtcvt_kernel<<<(VOCAB * H_ + 255) / 256, 256>>>();
    abv_kernel<<<(B_ * L_) / 8, H_>>>(hs, Wh_w);
    outinit_kernel<<<(B_ * C_ * L_ * L_ + 255) / 256, 256>>>(mask, Wo_b, out);
    dim3 grid(4, L_ / NI, B_);
    main_kernel<<<grid, NT, SMEM_TOTAL>>>(Wo_w, out);
}